// round 10
// baseline (speedup 1.0000x reference)
#include <cuda_runtime.h>

// ComNet: R=64 runs, T=256 timesteps, N=1024 agents, MLP 4->10(tanh)->2.
// Warp-autonomous strips: warp w owns timesteps [32w, 32w+32), lanes skewed 2
// apart, B=4 agent blocks, 318 private steps. Boundary comm row streamed via
// write-once smem rows; progress counter published only every 8 blocks
// (release), giving the consumer 1-8 blocks of slack so its cached check
// succeeds without synchronization on ~7/8 steps. No __syncthreads in loop.

#define R_  64
#define T_  256
#define N_  1024
#define NB_ 256            // agent blocks per row (N/4)
#define LSTEP_ 318         // 2*31 + 256 warp-local steps
#define PUBM_ 8            // publish granularity (blocks)

__device__ __forceinline__ float htanh(float x) {
    float r; asm("tanh.approx.f32 %0, %1;" : "=f"(r) : "f"(x)); return r;
}

__global__ __launch_bounds__(256, 1)
void comnet_kernel(const float* __restrict__ runs,
                   const float* __restrict__ comm0,
                   const float* __restrict__ w1,
                   const float* __restrict__ b1,
                   const float* __restrict__ w2,
                   const float* __restrict__ b2,
                   float* __restrict__ out)
{
    // boundary comm rows: warp w-1 writes rows4[w-1][0..255], warp w reads
    __shared__ float4 rows4[7][NB_];
    __shared__ int    cnt[7];          // published block progress per boundary

    const int r    = blockIdx.x;
    const int t    = threadIdx.x;      // global timestep role
    const int lane = t & 31;
    const int warp = t >> 5;

    if (t < 7) cnt[t] = 0;
    __syncthreads();                   // init visibility only

    const unsigned cnt_prev = (warp > 0)
        ? (unsigned)__cvta_generic_to_shared(&cnt[warp - 1]) : 0u;
    const unsigned cnt_me   = (warp < 7)
        ? (unsigned)__cvta_generic_to_shared(&cnt[warp]) : 0u;
    const float* rowf_prev = (warp > 0) ? (const float*)rows4[warp - 1]
                                        : (const float*)rows4[0];

    // ---- weights in registers ----
    float W1[40], B1[10], W2[20];
#pragma unroll
    for (int k = 0; k < 40; ++k) W1[k] = w1[k];
#pragma unroll
    for (int k = 0; k < 10; ++k) B1[k] = b1[k];
#pragma unroll
    for (int k = 0; k < 20; ++k) W2[k] = w2[k];
    const float B2lo = b2[0];
    const float B2hi = b2[1];

    const float4* __restrict__ xrow4 =
        (const float4*)(runs + ((size_t)r * T_ + t) * (size_t)N_ * 2);
    float4* __restrict__ orow4 = (float4*)(out + ((size_t)r * T_ + t) * N_);
    const float* __restrict__ c0row = comm0 + (size_t)r * N_;

    float4 h1 = make_float4(0.f, 0.f, 0.f, 0.f);   // own block @ local s-1
    float4 h2 = h1;                                // own block @ local s-2

    // prefetch block 0 inputs
    float4 px0 = xrow4[0];
    float4 px1 = xrow4[1];
    float4 pc0 = h1;
    if (t == 0) pc0 = make_float4(c0row[1], c0row[2], c0row[3], c0row[4]);

    int seen = 0;                      // cached published progress of producer

    for (int s = 0; s < LSTEP_; ++s) {
        const int b = s - 2 * lane;
        const bool active = ((unsigned)b < (unsigned)NB_);

        // ---- lane0 dependency check: cached fast path, rare poll ----
        if (lane == 0 && warp > 0 && active) {
            const int need = (b + 2 < NB_) ? (b + 2) : NB_;
            if (seen < need) {
                for (;;) {
                    asm volatile("ld.acquire.cta.shared.b32 %0, [%1];"
                                 : "=r"(seen) : "r"(cnt_prev) : "memory");
                    if (seen >= need) break;
                    __nanosleep(32);
                }
            }
        }

        // ---- right values c(t-1, 4b+1..4b+4): intra-warp via shuffles ----
        float r0 = __shfl_up_sync(0xffffffffu, h2.y, 1);
        float r1 = __shfl_up_sync(0xffffffffu, h2.z, 1);
        float r2 = __shfl_up_sync(0xffffffffu, h2.w, 1);
        float r3 = __shfl_up_sync(0xffffffffu, h1.x, 1);
        if (lane == 0) {
            if (warp > 0) {
                if (active) {
                    const float4 g = rows4[warp - 1][b];
                    r0 = g.y; r1 = g.z; r2 = g.w;
                    r3 = (b < NB_ - 1) ? rowf_prev[4 * b + 4] : 0.0f;
                }
            } else {   // t == 0: initial comm row
                r0 = pc0.x; r1 = pc0.y; r2 = pc0.z; r3 = pc0.w;
            }
        }
        if (b == NB_ - 1) r3 = 0.0f;   // zero right boundary for agent N-1

        const float4 cx0 = px0, cx1 = px1;

        // ---- prefetch next step's block inputs ----
        const int bn = s + 1 - 2 * lane;
        if ((unsigned)bn < (unsigned)NB_) {
            px0 = xrow4[2 * bn];
            px1 = xrow4[2 * bn + 1];
            if (t == 0) {
                const int base = 4 * bn;
                pc0 = make_float4(c0row[base + 1], c0row[base + 2],
                                  c0row[base + 3],
                                  (bn < NB_ - 1) ? c0row[base + 4] : 0.0f);
            }
        }

        float4 cur = h1;
        if (active) {
            float o0v[4], o1v[4];
            float lf = (b == 0) ? 0.0f : h1.w;     // c(t, 4b-1)
#pragma unroll
            for (int k = 0; k < 4; ++k) {
                const float xx = (k == 0) ? cx0.x : (k == 1) ? cx0.z
                                : (k == 2) ? cx1.x : cx1.z;
                const float xy = (k == 0) ? cx0.y : (k == 1) ? cx0.w
                                : (k == 2) ? cx1.y : cx1.w;
                const float rt = (k == 0) ? r0 : (k == 1) ? r1
                                : (k == 2) ? r2 : r3;

                float a0 = B2lo, a0b = 0.f, a1 = B2hi, a1b = 0.f;
#pragma unroll
                for (int j = 0; j < 10; ++j) {
                    float a = fmaf(W1[4 * j + 0], xx, B1[j]);
                    a       = fmaf(W1[4 * j + 1], xy, a);
                    a       = fmaf(W1[4 * j + 3], rt, a);
                    a       = fmaf(W1[4 * j + 2], lf, a);   // lf last: shortest chain
                    const float h = htanh(a);               // MUFU.TANH
                    if (j & 1) { a0b = fmaf(W2[j], h, a0b); a1b = fmaf(W2[10 + j], h, a1b); }
                    else       { a0  = fmaf(W2[j], h, a0);  a1  = fmaf(W2[10 + j], h, a1); }
                }
                o0v[k] = a0 + a0b;
                const float o1 = a1 + a1b;
                o1v[k] = o1;
                lf = o1;                           // left-chain within block
            }
            orow4[b] = make_float4(o0v[0], o0v[1], o0v[2], o0v[3]);
            cur = make_float4(o1v[0], o1v[1], o1v[2], o1v[3]);

            // ---- lane31 streams boundary row; publish progress every 8 ----
            if (lane == 31 && warp < 7) {
                rows4[warp][b] = cur;              // write-once slot
                if ((b & (PUBM_ - 1)) == PUBM_ - 1) {
                    asm volatile("st.release.cta.shared.b32 [%0], %1;"
                                 :: "r"(cnt_me), "r"(b + 1) : "memory");
                }
            }
        }

        h2 = h1;
        if (active) h1 = cur;
    }
}

extern "C" void kernel_launch(void* const* d_in, const int* in_sizes, int n_in,
                              void* d_out, int out_size)
{
    const float* runs  = (const float*)d_in[0];
    const float* comm0 = (const float*)d_in[1];
    const float* w1    = (const float*)d_in[2];
    const float* b1    = (const float*)d_in[3];
    const float* w2    = (const float*)d_in[4];
    const float* b2    = (const float*)d_in[5];
    float* out = (float*)d_out;

    comnet_kernel<<<R_, T_>>>(runs, comm0, w1, b1, w2, b2, out);
}

// round 12
// speedup vs baseline: 2.5520x; 2.5520x over previous
#include <cuda_runtime.h>

// ComNet: R=64 runs, T=256 timesteps, N=1024 agents, MLP 4->10(tanh)->2.
// STAGGERED wavefront, skew-1: row t's block b covers agents [4b-t, 4b-t+3].
// With this -1/row stagger, the right-deps of consumer (t, block b) are
// exactly producer (t-1, block b), element-for-element -> inter-thread skew
// is 1 step (vs 2), total steps 575 (vs 766). One CTA per run, 256 threads,
// shuffles + 2-phase smem ring + one __syncthreads per step. MUFU tanh.
// R12 fix: ring read phase is (s+1)&1 == (s-1)&1 (producer wrote at step s-1).

#define R_ 64
#define T_ 256
#define N_ 1024
#define NSTEP_ 575     // max_t (floor((1023+t)/4) + t) = 319 + 255, inclusive

__device__ __forceinline__ float htanh(float x) {
    float r; asm("tanh.approx.f32 %0, %1;" : "=f"(r) : "f"(x)); return r;
}
__device__ __forceinline__ int clampN(int a) {
    return a < 0 ? 0 : (a > N_ - 1 ? N_ - 1 : a);
}

__global__ __launch_bounds__(256, 1)
void comnet_kernel(const float* __restrict__ runs,
                   const float* __restrict__ comm0,
                   const float* __restrict__ w1,
                   const float* __restrict__ b1,
                   const float* __restrict__ w2,
                   const float* __restrict__ b2,
                   float* __restrict__ out)
{
    const int r    = blockIdx.x;
    const int t    = threadIdx.x;
    const int lane = t & 31;
    const int warp = t >> 5;

    // 2-phase ring: producer lane31 writes phase s&1 at its step s; consumer
    // lane0 of the next warp reads at step s+1 from phase (s+1+1)&1 = s&1.
    __shared__ float4 ring[2][8];

    // ---- weights in registers ----
    float W1[40], B1[10], W2[20];
#pragma unroll
    for (int k = 0; k < 40; ++k) W1[k] = w1[k];
#pragma unroll
    for (int k = 0; k < 10; ++k) B1[k] = b1[k];
#pragma unroll
    for (int k = 0; k < 20; ++k) W2[k] = w2[k];
    const float B2lo = b2[0];
    const float B2hi = b2[1];

    const float2* __restrict__ xrow2 =
        (const float2*)(runs + ((size_t)r * T_ + t) * (size_t)N_ * 2);
    float* __restrict__ orow = out + ((size_t)r * T_ + t) * N_;
    const float* __restrict__ c0row = comm0 + (size_t)r * N_;

    float4 h1 = make_float4(0.f, 0.f, 0.f, 0.f);   // own block @ s-1

    // prefetch for step 0 (agents A = -5t .. -5t+3, clamped; real only for t=0)
    float2 px[4];
    float  pc[4];
#pragma unroll
    for (int k = 0; k < 4; ++k) px[k] = xrow2[clampN(-5 * t + k)];
    if (t == 0) {
#pragma unroll
        for (int k = 0; k < 4; ++k) pc[k] = c0row[clampN(k + 1)];
    }

    for (int s = 0; s < NSTEP_; ++s) {
        const int b = s - t;
        const int A = 4 * b - t;                   // first agent of own block
        const bool active = (b >= 0) && (A <= N_ - 1) && (A >= -3);

        // ---- right values: producer (t-1) block b == my rt, elementwise ----
        float r0 = __shfl_up_sync(0xffffffffu, h1.x, 1);
        float r1 = __shfl_up_sync(0xffffffffu, h1.y, 1);
        float r2 = __shfl_up_sync(0xffffffffu, h1.z, 1);
        float r3 = __shfl_up_sync(0xffffffffu, h1.w, 1);
        if (lane == 0 && warp > 0) {
            const float4 g = ring[(s + 1) & 1][warp - 1];  // written at s-1
            r0 = g.x; r1 = g.y; r2 = g.z; r3 = g.w;
        }
        if (t == 0) { r0 = pc[0]; r1 = pc[1]; r2 = pc[2]; r3 = pc[3]; }

        const float2 cx0 = px[0], cx1 = px[1], cx2 = px[2], cx3 = px[3];

        // ---- prefetch next step's block (A+4 .. A+7, clamped) ----
        {
            const int An = A + 4;
#pragma unroll
            for (int k = 0; k < 4; ++k) px[k] = xrow2[clampN(An + k)];
            if (t == 0) {
#pragma unroll
                for (int k = 0; k < 4; ++k) pc[k] = c0row[clampN(An + k + 1)];
            }
        }

        if (active) {
            float o1v[4];
            float lf = h1.w;                        // c(t, A-1)
#pragma unroll
            for (int k = 0; k < 4; ++k) {
                const int a = A + k;                // agent index
                const float xx = (k == 0) ? cx0.x : (k == 1) ? cx1.x
                                : (k == 2) ? cx2.x : cx3.x;
                const float xy = (k == 0) ? cx0.y : (k == 1) ? cx1.y
                                : (k == 2) ? cx2.y : cx3.y;
                float rt = (k == 0) ? r0 : (k == 1) ? r1
                          : (k == 2) ? r2 : r3;
                rt = (a >= N_ - 1) ? 0.0f : rt;     // zero right boundary
                const float lfu = (a == 0) ? 0.0f : lf;  // zero left boundary

                float a0 = B2lo, a0b = 0.f, a1 = B2hi, a1b = 0.f;
#pragma unroll
                for (int j = 0; j < 10; ++j) {
                    float v = fmaf(W1[4 * j + 0], xx,  B1[j]);
                    v       = fmaf(W1[4 * j + 1], xy,  v);
                    v       = fmaf(W1[4 * j + 3], rt,  v);
                    v       = fmaf(W1[4 * j + 2], lfu, v);  // lf last: shortest chain
                    const float h = htanh(v);               // MUFU.TANH
                    if (j & 1) { a0b = fmaf(W2[j], h, a0b); a1b = fmaf(W2[10 + j], h, a1b); }
                    else       { a0  = fmaf(W2[j], h, a0);  a1  = fmaf(W2[10 + j], h, a1); }
                }
                const float o0 = a0 + a0b;
                const float o1 = a1 + a1b;
                if ((unsigned)a <= (unsigned)(N_ - 1)) orow[a] = o0;
                o1v[k] = o1;
                lf = o1;                            // left-chain within block
            }
            const float4 cur = make_float4(o1v[0], o1v[1], o1v[2], o1v[3]);
            h1 = cur;
            if (lane == 31) ring[s & 1][warp] = cur;
        }

        __syncthreads();
    }
}

extern "C" void kernel_launch(void* const* d_in, const int* in_sizes, int n_in,
                              void* d_out, int out_size)
{
    const float* runs  = (const float*)d_in[0];
    const float* comm0 = (const float*)d_in[1];
    const float* w1    = (const float*)d_in[2];
    const float* b1    = (const float*)d_in[3];
    const float* w2    = (const float*)d_in[4];
    const float* b2    = (const float*)d_in[5];
    float* out = (float*)d_out;

    comnet_kernel<<<R_, T_>>>(runs, comm0, w1, b1, w2, b2, out);
}